// round 11
// baseline (speedup 1.0000x reference)
#include <cuda_runtime.h>
#include <cstdint>

// CrossMerge3D: out[b,c,i,j,k] = ( sum of 12 scans in 3 orientations ) / 12
//   family i (s=0..3):  n = i*1024 + j*32 + k   (fwd s0,s1; flipped s2,s3)
//   family j (s=4..7):  n = j*1024 + k*32 + i
//   family k (s=8..11): n = k*1024 + i*32 + j
//
// Block = (b, c, i-slab of 4), 256 threads, 33KB smem, 6 blocks/SM.
// SINGLE-BARRIER, ZERO-RMW structure:
//   front loop: each iteration loads one family-j chunk AND one family-k
//     chunk (8 independent LDG.128/thread) and plain-stores them into two
//     disjoint smem regions (no read-modify-write anywhere).
//   __syncthreads()  (the only barrier)
//   epilogue: family i loads + out = (acc_j + acc_k + fam_i)/12,
//     float4 streaming stores (proven contiguous shape).

#define DD      32
#define NVOL    32768            // 32^3
#define CCH     96
#define CN      (CCH * NVOL)     // 3145728
#define SLAB_I  4
#define NSLAB   (DD / SLAB_I)    // 8
#define SLAB_N  (SLAB_I * DD * DD)   // 4096
#define THREADS 256
#define CHUNKS  (SLAB_N / 4)     // 1024 float4-chunks per family
#define ITERS   (CHUNKS / THREADS)   // 4

// padded smem index: injective (per-ii span 0..1054 < 1060),
// bank(f) = (4*ii + j + k) mod 32  (1060 mod 32 = 4, 33 mod 32 = 1)
#define STRIDE_II 1060
#define REGION    (3 * STRIDE_II + 31 * 33 + 31 + 2)   // 4236 floats
__device__ __forceinline__ int fidx(int ii, int j, int k) {
    return ii * STRIDE_II + j * 33 + k;
}

__global__ __launch_bounds__(THREADS)
void cross_merge3d_kernel(const float* __restrict__ ys, float* __restrict__ out) {
    __shared__ float acc_j[REGION];
    __shared__ float acc_k[REGION];

    const int bid = blockIdx.x;
    const int a   = bid & (NSLAB - 1);        // i-slab (0..7)
    const int c   = (bid >> 3) % CCH;
    const int b   = bid / (NSLAB * CCH);
    const int tid = threadIdx.x;

    const float* base = ys + (size_t)b * (12 * (size_t)CN) + (size_t)c * NVOL;

    // ---------------- Fused front: families j and k, plain stores ----------------
    {
        const float* q4  = base + 4  * (size_t)CN;
        const float* q5  = base + 5  * (size_t)CN;
        const float* q6  = base + 6  * (size_t)CN;
        const float* q7  = base + 7  * (size_t)CN;
        const float* q8  = base + 8  * (size_t)CN;
        const float* q9  = base + 9  * (size_t)CN;
        const float* q10 = base + 10 * (size_t)CN;
        const float* q11 = base + 11 * (size_t)CN;
        #pragma unroll 1
        for (int it = 0; it < ITERS; it++) {
            int chunk = it * THREADS + tid;

            // family j mapping: n = j*1024 + k*32 + i, i = 4a..4a+3
            int kj = chunk & 31;
            int jj = chunk >> 5;
            int mj = jj * 1024 + kj * 32 + a * SLAB_I;
            // family k mapping: n = k*1024 + i*32 + j, j = 4*j4..4*j4+3
            int j4 = chunk & 7;
            int kk = (chunk >> 3) & 31;
            int ii = chunk >> 8;                // 0..3
            int mk = kk * 1024 + (a * SLAB_I + ii) * 32 + 4 * j4;

            // 8 independent 16B loads — one big MLP batch
            float4 f4 = *(const float4*)(q4 + mj);
            float4 f5 = *(const float4*)(q5 + mj);
            int rj = NVOL - 4 - mj;
            float4 r6 = *(const float4*)(q6 + rj);
            float4 r7 = *(const float4*)(q7 + rj);
            float4 f8 = *(const float4*)(q8 + mk);
            float4 f9 = *(const float4*)(q9 + mk);
            int rk = NVOL - 4 - mk;
            float4 rA = *(const float4*)(q10 + rk);
            float4 rB = *(const float4*)(q11 + rk);

            // family j -> acc_j (banks (4e + jj + kj): 32-distinct per warp)
            acc_j[fidx(0, jj, kj)] = f4.x + f5.x + r6.w + r7.w;
            acc_j[fidx(1, jj, kj)] = f4.y + f5.y + r6.z + r7.z;
            acc_j[fidx(2, jj, kj)] = f4.z + f5.z + r6.y + r7.y;
            acc_j[fidx(3, jj, kj)] = f4.w + f5.w + r6.x + r7.x;

            // family k -> acc_k (banks (4ii + 4j4 + e + kk): 32-distinct per warp)
            int jb = 4 * j4;
            acc_k[fidx(ii, jb + 0, kk)] = f8.x + f9.x + rA.w + rB.w;
            acc_k[fidx(ii, jb + 1, kk)] = f8.y + f9.y + rA.z + rB.z;
            acc_k[fidx(ii, jb + 2, kk)] = f8.z + f9.z + rA.y + rB.y;
            acc_k[fidx(ii, jb + 3, kk)] = f8.w + f9.w + rA.x + rB.x;
        }
    }
    __syncthreads();   // the only barrier

    // ---------------- Epilogue: family i (s = 0..3) + fused output ----------------
    // n = i*1024 + j*32 + k. Threads own contiguous output cells ->
    // float4 streaming stores.
    {
        const float* q0 = base + 0 * (size_t)CN;
        const float* q1 = base + 1 * (size_t)CN;
        const float* q2 = base + 2 * (size_t)CN;
        const float* q3 = base + 3 * (size_t)CN;
        float* ob = out + ((size_t)b * CCH + c) * NVOL + a * SLAB_N;
        const float s = 1.0f / 12.0f;
        #pragma unroll
        for (int it = 0; it < ITERS; it++) {
            int chunk   = it * THREADS + tid;
            int n_local = chunk * 4;
            int ii = n_local >> 10;               // 0..3
            int j  = (n_local >> 5) & 31;
            int k  = n_local & 31;
            int n_g = a * SLAB_N + n_local;
            float4 f0 = *(const float4*)(q0 + n_g);
            float4 f1 = *(const float4*)(q1 + n_g);
            int r_g = NVOL - 4 - n_g;
            float4 r2 = *(const float4*)(q2 + r_g);
            float4 r3 = *(const float4*)(q3 + r_g);
            int f = fidx(ii, j, k);
            float4 o;
            o.x = (acc_j[f + 0] + acc_k[f + 0] + f0.x + f1.x + r2.w + r3.w) * s;
            o.y = (acc_j[f + 1] + acc_k[f + 1] + f0.y + f1.y + r2.z + r3.z) * s;
            o.z = (acc_j[f + 2] + acc_k[f + 2] + f0.z + f1.z + r2.y + r3.y) * s;
            o.w = (acc_j[f + 3] + acc_k[f + 3] + f0.w + f1.w + r2.x + r3.x) * s;
            __stcs((float4*)(ob + n_local), o);
        }
    }
}

extern "C" void kernel_launch(void* const* d_in, const int* in_sizes, int n_in,
                              void* d_out, int out_size) {
    const float* ys = (const float*)d_in[0];
    float* out = (float*)d_out;
    // grid = B * C * slabs = 2 * 96 * 8 = 1536
    cross_merge3d_kernel<<<1536, THREADS>>>(ys, out);
}

// round 12
// speedup vs baseline: 1.8655x; 1.8655x over previous
#include <cuda_runtime.h>
#include <cstdint>

// CrossMerge3D: out[b,c,i,j,k] = ( sum of 12 scans in 3 orientations ) / 12
//   family i (s=0..3):  n = i*1024 + j*32 + k   (fwd s0,s1; flipped s2,s3)
//   family j (s=4..7):  n = j*1024 + k*32 + i
//   family k (s=8..11): n = k*1024 + i*32 + j
//
// Block = (b, c, j-half, i-slab of 4), 256 threads, ~9KB smem.
// Same proven 3-phase structure as the 59.9us kernel (j-store, k-RMW,
// i-loads + fused float4 __stcs epilogue), but the work quantum is halved
// along j: grid 3072 -> ~21 units/SM -> wave-quantization imbalance ~5%
// instead of ~10%, finer end-of-kernel skew. ITERS=2, fully unrolled.
//
// smem padding for the j-split: fidx = ii*560 + j*35 + k
//   injective: per-ii span = 15*35+31 = 556 < 560
//   phase-j stores: lanes kj 0..31 -> 32 distinct banks
//   phase-k RMW:    banks 12*j4 + 3e + kk over {0,12,24,4}+{0..7} -> distinct
//   epilogue LDS:   banks 3*j' + 4*k4 + e over 4x8 lattice -> distinct

#define DD      32
#define NVOL    32768            // 32^3
#define CCH     96
#define CN      (CCH * NVOL)     // 3145728
#define SLAB_I  4
#define NSLAB   8
#define JHALF   16
#define THREADS 256
#define CHUNKS  512              // (4 ii * 16 j * 32 k) / 4 per phase
#define ITERS   (CHUNKS / THREADS)   // 2

#define S_J   35
#define S_II  560
#define REGION (3 * S_II + 15 * S_J + 31 + 4)   // 2240 floats (~9KB)
__device__ __forceinline__ int fidx(int ii, int j, int k) {
    return ii * S_II + j * S_J + k;
}

__global__ __launch_bounds__(THREADS)
void cross_merge3d_kernel(const float* __restrict__ ys, float* __restrict__ out) {
    __shared__ float acc[REGION];

    const int bid = blockIdx.x;
    const int a   = bid & 7;                  // i-slab (i = 4a+ii)
    const int jh  = (bid >> 3) & 1;           // j-half
    const int c   = (bid >> 4) % CCH;
    const int b   = bid / (16 * CCH);
    const int tid = threadIdx.x;
    const int job = jh * JHALF;               // j offset

    const float* base = ys + (size_t)b * (12 * (size_t)CN) + (size_t)c * NVOL;

    // ---------------- Phase 1: family j (s = 4..7), init accumulator ----------------
    // n = j*1024 + k*32 + i; float4 covers i = 4a..4a+3 (element e <-> ii=e)
    {
        const float* q4 = base + 4 * (size_t)CN;
        const float* q5 = base + 5 * (size_t)CN;
        const float* q6 = base + 6 * (size_t)CN;
        const float* q7 = base + 7 * (size_t)CN;
        #pragma unroll
        for (int it = 0; it < ITERS; it++) {
            int chunk = it * THREADS + tid;
            int kj = chunk & 31;
            int jl = chunk >> 5;              // 0..15
            int m  = (job + jl) * 1024 + kj * 32 + a * SLAB_I;
            float4 f4 = *(const float4*)(q4 + m);
            float4 f5 = *(const float4*)(q5 + m);
            int r_m = NVOL - 4 - m;
            float4 r6 = *(const float4*)(q6 + r_m);
            float4 r7 = *(const float4*)(q7 + r_m);
            acc[fidx(0, jl, kj)] = f4.x + f5.x + r6.w + r7.w;
            acc[fidx(1, jl, kj)] = f4.y + f5.y + r6.z + r7.z;
            acc[fidx(2, jl, kj)] = f4.z + f5.z + r6.y + r7.y;
            acc[fidx(3, jl, kj)] = f4.w + f5.w + r6.x + r7.x;
        }
    }
    __syncthreads();

    // ---------------- Phase 2: family k (s = 8..11), acc += ----------------
    // n = k*1024 + i*32 + j; float4 covers j = job+4*j4 .. +3
    {
        const float* q8  = base + 8  * (size_t)CN;
        const float* q9  = base + 9  * (size_t)CN;
        const float* q10 = base + 10 * (size_t)CN;
        const float* q11 = base + 11 * (size_t)CN;
        #pragma unroll
        for (int it = 0; it < ITERS; it++) {
            int chunk = it * THREADS + tid;
            int j4 = chunk & 3;                 // j' = 4*j4 + e
            int kk = (chunk >> 2) & 31;
            int ii = chunk >> 7;                // 0..3
            int m  = kk * 1024 + (a * SLAB_I + ii) * 32 + job + 4 * j4;
            float4 f8 = *(const float4*)(q8  + m);
            float4 f9 = *(const float4*)(q9  + m);
            int r_m = NVOL - 4 - m;
            float4 rA = *(const float4*)(q10 + r_m);
            float4 rB = *(const float4*)(q11 + r_m);
            int jb = 4 * j4;
            acc[fidx(ii, jb + 0, kk)] += f8.x + f9.x + rA.w + rB.w;
            acc[fidx(ii, jb + 1, kk)] += f8.y + f9.y + rA.z + rB.z;
            acc[fidx(ii, jb + 2, kk)] += f8.z + f9.z + rA.y + rB.y;
            acc[fidx(ii, jb + 3, kk)] += f8.w + f9.w + rA.x + rB.x;
        }
    }
    __syncthreads();

    // ---------------- Phase 3: family i (s = 0..3) + fused epilogue ----------------
    // n = i*1024 + j*32 + k; threads own contiguous k -> float4 loads+stores
    {
        const float* q0 = base + 0 * (size_t)CN;
        const float* q1 = base + 1 * (size_t)CN;
        const float* q2 = base + 2 * (size_t)CN;
        const float* q3 = base + 3 * (size_t)CN;
        float* obc = out + ((size_t)b * CCH + c) * NVOL;
        const float s = 1.0f / 12.0f;
        #pragma unroll
        for (int it = 0; it < ITERS; it++) {
            int chunk = it * THREADS + tid;
            int k4 = chunk & 7;                 // k = 4*k4 + e
            int jl = (chunk >> 3) & 15;
            int ii = chunk >> 7;                // 0..3
            int n_g = (a * SLAB_I + ii) * 1024 + (job + jl) * 32 + 4 * k4;
            float4 f0 = *(const float4*)(q0 + n_g);
            float4 f1 = *(const float4*)(q1 + n_g);
            int r_g = NVOL - 4 - n_g;
            float4 r2 = *(const float4*)(q2 + r_g);
            float4 r3 = *(const float4*)(q3 + r_g);
            int f = fidx(ii, jl, 4 * k4);
            float4 o;
            o.x = (acc[f + 0] + f0.x + f1.x + r2.w + r3.w) * s;
            o.y = (acc[f + 1] + f0.y + f1.y + r2.z + r3.z) * s;
            o.z = (acc[f + 2] + f0.z + f1.z + r2.y + r3.y) * s;
            o.w = (acc[f + 3] + f0.w + f1.w + r2.x + r3.x) * s;
            __stcs((float4*)(obc + n_g), o);
        }
    }
}

extern "C" void kernel_launch(void* const* d_in, const int* in_sizes, int n_in,
                              void* d_out, int out_size) {
    const float* ys = (const float*)d_in[0];
    float* out = (float*)d_out;
    // grid = B * C * j-halves * i-slabs = 2 * 96 * 2 * 8 = 3072
    cross_merge3d_kernel<<<3072, THREADS>>>(ys, out);
}

// round 13
// speedup vs baseline: 1.9329x; 1.0361x over previous
#include <cuda_runtime.h>
#include <cstdint>

// CrossMerge3D: out[b,c,i,j,k] = ( sum of 12 scans in 3 orientations ) / 12
//   family i (s=0..3):  n = i*1024 + j*32 + k   (fwd s0,s1; flipped s2,s3)
//   family j (s=4..7):  n = j*1024 + k*32 + i
//   family k (s=8..11): n = k*1024 + i*32 + j
//
// Block = (b, c, j-half, i-quarter): 8i x 16j x 32k = 4096 cells, grid 1536.
// 2-D split maximizes bytes-per-touched-L1-line in every family:
//   family j: 32B/line, family k: 64B/line, family i: 128B/line
//   -> 0.91 L1tex wavefronts/cell vs 1.5 in the 57.8us i-only split.
// smem: f(row,k) = row*36 + (k ^ s(row)), row = ii*16+jl,
//       s = (8*((row>>2)&3)) ^ (16*(row>>6))
//   injective; P1 stores / P2 RMW conflict-free; epilogue is an aligned,
//   conflict-free LDS.128 (vector) load. Streaming float4 output stores.

#define DD      32
#define NVOL    32768            // 32^3
#define CCH     96
#define CN      (CCH * NVOL)     // 3145728
#define THREADS 256
#define ITERS   4                // 1024 float4-chunks per family / 256 threads

__global__ __launch_bounds__(THREADS)
void cross_merge3d_kernel(const float* __restrict__ ys, float* __restrict__ out) {
    __shared__ __align__(16) float acc[128 * 36];   // 4608 floats (18.4KB)

    const int bid = blockIdx.x;
    const int ia  = bid & 3;                  // i-quarter (i = 8*ia + ii)
    const int jh  = (bid >> 2) & 1;           // j-half
    const int c   = (bid >> 3) % CCH;
    const int b   = bid / (8 * CCH);
    const int tid = threadIdx.x;
    const int job = jh * 16;                  // j offset

    const float* base = ys + (size_t)b * (12 * (size_t)CN) + (size_t)c * NVOL;

    // ---------------- Phase 1: family j (s = 4..7), init accumulator ----------------
    // n = j*1024 + k*32 + i; float4 covers i = 8*ia + 4*ih4 .. +3
    {
        const float* q4 = base + 4 * (size_t)CN;
        const float* q5 = base + 5 * (size_t)CN;
        const float* q6 = base + 6 * (size_t)CN;
        const float* q7 = base + 7 * (size_t)CN;
        #pragma unroll
        for (int it = 0; it < ITERS; it++) {
            int chunk = it * THREADS + tid;
            int ih4 = chunk & 1;
            int kj  = (chunk >> 1) & 31;
            int jl  = chunk >> 6;             // 0..15
            int m   = (job + jl) * 1024 + kj * 32 + ia * 8 + 4 * ih4;
            float4 f4 = *(const float4*)(q4 + m);
            float4 f5 = *(const float4*)(q5 + m);
            int r_m = NVOL - 4 - m;
            float4 r6 = *(const float4*)(q6 + r_m);
            float4 r7 = *(const float4*)(q7 + r_m);
            int sw = (8 * ((jl >> 2) & 3)) ^ (16 * ih4);
            int f0 = (ih4 * 64 + jl) * 36 + (kj ^ sw);   // row(e) = 64*ih4+16*e+jl
            acc[f0 +    0] = f4.x + f5.x + r6.w + r7.w;
            acc[f0 +  576] = f4.y + f5.y + r6.z + r7.z;
            acc[f0 + 1152] = f4.z + f5.z + r6.y + r7.y;
            acc[f0 + 1728] = f4.w + f5.w + r6.x + r7.x;
        }
    }
    __syncthreads();

    // ---------------- Phase 2: family k (s = 8..11), acc += ----------------
    // n = k*1024 + i*32 + j; float4 covers j = job + 4*j4 .. +3
    {
        const float* q8  = base + 8  * (size_t)CN;
        const float* q9  = base + 9  * (size_t)CN;
        const float* q10 = base + 10 * (size_t)CN;
        const float* q11 = base + 11 * (size_t)CN;
        #pragma unroll
        for (int it = 0; it < ITERS; it++) {
            int chunk = it * THREADS + tid;
            int j4 = chunk & 3;
            int kk = (chunk >> 2) & 31;
            int ii = chunk >> 7;              // 0..7
            int m  = kk * 1024 + (ia * 8 + ii) * 32 + job + 4 * j4;
            float4 f8 = *(const float4*)(q8  + m);
            float4 f9 = *(const float4*)(q9  + m);
            int r_m = NVOL - 4 - m;
            float4 rA = *(const float4*)(q10 + r_m);
            float4 rB = *(const float4*)(q11 + r_m);
            int sw = (8 * j4) ^ (16 * (ii >> 2));
            int f0 = (ii * 16 + 4 * j4) * 36 + (kk ^ sw);   // row(e) = ii*16+4*j4+e
            acc[f0 +   0] += f8.x + f9.x + rA.w + rB.w;
            acc[f0 +  36] += f8.y + f9.y + rA.z + rB.z;
            acc[f0 +  72] += f8.z + f9.z + rA.y + rB.y;
            acc[f0 + 108] += f8.w + f9.w + rA.x + rB.x;
        }
    }
    __syncthreads();

    // ---------------- Phase 3: family i (s = 0..3) + fused epilogue ----------------
    // n = i*1024 + j*32 + k; threads own contiguous k -> LDS.128 + STG.128
    {
        const float* q0 = base + 0 * (size_t)CN;
        const float* q1 = base + 1 * (size_t)CN;
        const float* q2 = base + 2 * (size_t)CN;
        const float* q3 = base + 3 * (size_t)CN;
        float* obc = out + ((size_t)b * CCH + c) * NVOL;
        const float s12 = 1.0f / 12.0f;
        #pragma unroll
        for (int it = 0; it < ITERS; it++) {
            int chunk = it * THREADS + tid;
            int k4 = chunk & 7;
            int jl = (chunk >> 3) & 15;
            int ii = chunk >> 7;              // 0..7
            int n_g = (ia * 8 + ii) * 1024 + (job + jl) * 32 + 4 * k4;
            float4 f0 = *(const float4*)(q0 + n_g);
            float4 f1 = *(const float4*)(q1 + n_g);
            int r_g = NVOL - 4 - n_g;
            float4 r2 = *(const float4*)(q2 + r_g);
            float4 r3 = *(const float4*)(q3 + r_g);
            int sw = (8 * ((jl >> 2) & 3)) ^ (16 * (ii >> 2));
            int f  = (ii * 16 + jl) * 36 + ((4 * k4) ^ sw);  // 16B-aligned
            float4 av = *(const float4*)(acc + f);
            float4 o;
            o.x = (av.x + f0.x + f1.x + r2.w + r3.w) * s12;
            o.y = (av.y + f0.y + f1.y + r2.z + r3.z) * s12;
            o.z = (av.z + f0.z + f1.z + r2.y + r3.y) * s12;
            o.w = (av.w + f0.w + f1.w + r2.x + r3.x) * s12;
            __stcs((float4*)(obc + n_g), o);
        }
    }
}

extern "C" void kernel_launch(void* const* d_in, const int* in_sizes, int n_in,
                              void* d_out, int out_size) {
    const float* ys = (const float*)d_in[0];
    float* out = (float*)d_out;
    // grid = B * C * j-halves * i-quarters = 2 * 96 * 2 * 4 = 1536
    cross_merge3d_kernel<<<1536, THREADS>>>(ys, out);
}